// round 12
// baseline (speedup 1.0000x reference)
#include <cuda_runtime.h>
#include <cuda_fp16.h>
#include <cstdint>

#define B_ 16
#define S_ 2048
#define D_ 128
#define SCALE_ 0.08838834764831845f  // 1/sqrt(128)

#define QLD_ 136   // halves per Q/K smem row (128 data + 8 pad)
#define HLD_ 48    // halves per P smem row (32 data + 16 pad)
#define VLD_ 136   // words per Vs2 row (128 data + 8 pad)

__device__ __forceinline__ uint32_t h2u(half2 h) {
    union { half2 h; uint32_t u; } cvt;
    cvt.h = h;
    return cvt.u;
}

__device__ __forceinline__ uint32_t smem_u32(const void* p) {
    uint32_t a;
    asm("{ .reg .u64 t; cvta.to.shared.u64 t, %1; cvt.u32.u64 %0, t; }" : "=r"(a) : "l"(p));
    return a;
}

// D += A*B, m16n8k16 f16 (f32 accum)
__device__ __forceinline__ void mma16(float* d, uint32_t a0, uint32_t a1, uint32_t a2,
                                      uint32_t a3, uint32_t b0, uint32_t b1) {
    asm volatile(
        "mma.sync.aligned.m16n8k16.row.col.f32.f16.f16.f32 "
        "{%0,%1,%2,%3}, {%4,%5,%6,%7}, {%8,%9}, {%0,%1,%2,%3};"
        : "+f"(d[0]), "+f"(d[1]), "+f"(d[2]), "+f"(d[3])
        : "r"(a0), "r"(a1), "r"(a2), "r"(a3), "r"(b0), "r"(b1));
}

#define LDSM4(r0, r1, r2, r3, a) \
    asm volatile("ldmatrix.sync.aligned.m8n8.x4.shared.b16 {%0,%1,%2,%3}, [%4];" \
                 : "=r"(r0), "=r"(r1), "=r"(r2), "=r"(r3) : "r"(a))

// Convert float4 -> 4 halves, one STS.64
__device__ __forceinline__ void store_h4(half* rowp, int c4, float4 v) {
    uint2 u = { h2u(__floats2half2_rn(v.x, v.y)), h2u(__floats2half2_rn(v.z, v.w)) };
    *(uint2*)(rowp + c4) = u;
}

// Permuted half store (out_mma P layout)
__device__ __forceinline__ void store_perm(half* rowp, int c4, float4 v) {
    const int kk0 = c4 & 15;
    const int pos = ((c4 >> 4) << 4) + ((kk0 & 7) << 1) + ((kk0 >> 3) << 1);
    *(half2*)(rowp + pos)     = __floats2half2_rn(v.x, v.y);
    *(half2*)(rowp + pos + 4) = __floats2half2_rn(v.z, v.w);
}

// =====================================================================
// Kernel 1: scores[b,q,k] = (Q.K^T)*SCALE + mask
// CTA 128x128, full-depth single fill, ONE barrier.
// 4 warps (128 thr) = 2(m) x 2(n); warp tile 64x64 -> 32 flop/LDS-byte.
// =====================================================================
#define S_SMEM (2 * 128 * QLD_ * 2)   // 69632 B dynamic

__global__ __launch_bounds__(128, 2) void scores_mma(
    const float* __restrict__ q, const float* __restrict__ k,
    const float* __restrict__ mask, float* __restrict__ attn)
{
    extern __shared__ half sm[];
    half* Qh = sm;                 // [128][QLD_]
    half* Kh = sm + 128 * QLD_;    // [128][QLD_]

    const int b  = blockIdx.x;
    const int kt = blockIdx.y * 128;
    const int qt = blockIdx.z * 128;

    const float* qb = q + ((size_t)b * S_ + qt) * D_;
    const float* kb = k + ((size_t)b * S_ + kt) * D_;

    const int tid  = threadIdx.x;
    const int wid  = tid >> 5, lane = tid & 31;
    const int g    = lane >> 2, c = lane & 3;
    const int wm   = (wid & 1) * 64;
    const int wn   = (wid >> 1) * 64;

    const uint32_t qbase = smem_u32(Qh);
    const uint32_t kbase = smem_u32(Kh);
    const int l15 = lane & 15;
    const int khi = (lane >> 4) << 3;

    float acc[4][8][4];
#pragma unroll
    for (int mi = 0; mi < 4; mi++)
#pragma unroll
        for (int ni = 0; ni < 8; ni++)
#pragma unroll
            for (int r = 0; r < 4; r++) acc[mi][ni][r] = 0.0f;

    // ---- single fill: full 128x128 Q and K tiles (128 threads) ----
#pragma unroll
    for (int t = 0; t < 32; t++) {
        const int idx = tid + t * 128;
        const int row = idx >> 5, c4 = (idx & 31) * 4;
        const float4 vq = *(const float4*)&qb[(size_t)row * D_ + c4];
        const float4 vk = *(const float4*)&kb[(size_t)row * D_ + c4];
        store_h4(&Qh[row * QLD_], c4, vq);
        store_h4(&Kh[row * QLD_], c4, vk);
    }
    __syncthreads();

    // ---- 8 k-steps, no barriers ----
#pragma unroll
    for (int kq = 0; kq < 8; kq++) {
        const int koff = kq * 16 + khi;
        uint32_t b0[8], b1[8];
#pragma unroll
        for (int bg = 0; bg < 4; bg++) {
            const uint32_t a = kbase +
                (uint32_t)(((wn + bg * 16 + l15) * QLD_ + koff) << 1);
            LDSM4(b0[2 * bg], b0[2 * bg + 1], b1[2 * bg], b1[2 * bg + 1], a);
        }
#pragma unroll
        for (int mi = 0; mi < 4; mi++) {
            uint32_t a0, a1, a2, a3;
            const uint32_t a = qbase +
                (uint32_t)(((wm + mi * 16 + l15) * QLD_ + koff) << 1);
            LDSM4(a0, a1, a2, a3, a);
#pragma unroll
            for (int ni = 0; ni < 8; ni++)
                mma16(acc[mi][ni], a0, a1, a2, a3, b0[ni], b1[ni]);
        }
    }

    // ---- epilogue: scale + mask ----
#pragma unroll
    for (int mi = 0; mi < 4; mi++) {
#pragma unroll
        for (int rr = 0; rr < 2; rr++) {
            const int qrow = qt + wm + mi * 16 + g + rr * 8;
            const float* mrow = mask + (size_t)qrow * S_ + kt;
            float* arow = attn + ((size_t)b * S_ + qrow) * S_ + kt;
#pragma unroll
            for (int ni = 0; ni < 8; ni++) {
                const int col = wn + ni * 8 + c * 2;
                const float2 m2 = *(const float2*)&mrow[col];
                float2 o;
                o.x = acc[mi][ni][rr * 2 + 0] * SCALE_ + m2.x;
                o.y = acc[mi][ni][rr * 2 + 1] * SCALE_ + m2.y;
                *(float2*)&arow[col] = o;
            }
        }
    }
}

// =====================================================================
// Kernel 2: in-place row softmax. One 256-thread CTA per row.
// =====================================================================
__global__ __launch_bounds__(256) void softmax_kernel(float* __restrict__ attn)
{
    __shared__ float red[256];
    const size_t row = blockIdx.x;
    float* p = attn + row * (size_t)S_;
    const int tid = threadIdx.x;

    float4 v0 = ((const float4*)p)[tid];
    float4 v1 = ((const float4*)p)[tid + 256];

    float m = fmaxf(fmaxf(fmaxf(v0.x, v0.y), fmaxf(v0.z, v0.w)),
                    fmaxf(fmaxf(v1.x, v1.y), fmaxf(v1.z, v1.w)));
    red[tid] = m;
    __syncthreads();
#pragma unroll
    for (int s = 128; s > 0; s >>= 1) {
        if (tid < s) red[tid] = fmaxf(red[tid], red[tid + s]);
        __syncthreads();
    }
    m = red[0];
    __syncthreads();

    v0.x = __expf(v0.x - m); v0.y = __expf(v0.y - m);
    v0.z = __expf(v0.z - m); v0.w = __expf(v0.w - m);
    v1.x = __expf(v1.x - m); v1.y = __expf(v1.y - m);
    v1.z = __expf(v1.z - m); v1.w = __expf(v1.w - m);

    float sum = (v0.x + v0.y) + (v0.z + v0.w) + (v1.x + v1.y) + (v1.z + v1.w);
    red[tid] = sum;
    __syncthreads();
#pragma unroll
    for (int s = 128; s > 0; s >>= 1) {
        if (tid < s) red[tid] += red[tid + s];
        __syncthreads();
    }
    const float inv = 1.0f / red[0];

    v0.x *= inv; v0.y *= inv; v0.z *= inv; v0.w *= inv;
    v1.x *= inv; v1.y *= inv; v1.z *= inv; v1.w *= inv;
    ((float4*)p)[tid]       = v0;
    ((float4*)p)[tid + 256] = v1;
}

// =====================================================================
// Kernel 3: out[b,q,d] = sum_s P[b,q,s] * V[b,s,d]   (round-8/11 exact)
// =====================================================================
__global__ __launch_bounds__(256, 2) void out_mma(
    const float* __restrict__ attn, const float* __restrict__ v,
    float* __restrict__ out)
{
    __shared__ half Ph[128 * HLD_];
    __shared__ uint32_t Vs2[16 * VLD_];

    const int b  = blockIdx.x;
    const int qt = blockIdx.y * 128;

    const float* pb = attn + ((size_t)b * S_ + qt) * S_;
    const float* vb = v + (size_t)b * S_ * D_;

    const int tid  = threadIdx.x;
    const int wid  = tid >> 5, lane = tid & 31;
    const int g    = lane >> 2, c = lane & 3;
    const int wm   = (wid & 1) * 64;
    const int wn   = (wid >> 1) * 32;

    const int pr    = tid >> 4;
    const int dbase = (tid & 15) * 4;

    float acc[4][4][4];
#pragma unroll
    for (int mi = 0; mi < 4; mi++)
#pragma unroll
        for (int ni = 0; ni < 4; ni++)
#pragma unroll
            for (int r = 0; r < 4; r++) acc[mi][ni][r] = 0.0f;

#pragma unroll 1
    for (int k0 = 0; k0 < S_; k0 += 32) {
#pragma unroll
        for (int t = 0; t < 4; t++) {
            const int idx = tid + t * 256;
            const int row = idx >> 3, c4 = (idx & 7) * 4;
            const float4 vp = *(const float4*)&pb[(size_t)row * S_ + k0 + c4];
            store_perm(&Ph[row * HLD_], c4, vp);
        }
        {
            const float* v0r = vb + (size_t)(k0 + 2 * pr) * D_;
            const float* v1r = v0r + D_;
#pragma unroll
            for (int h = 0; h < 2; h++) {
                const int d = dbase + h * 64;
                const float4 a = *(const float4*)&v0r[d];
                const float4 bb = *(const float4*)&v1r[d];
                uint4 u;
                u.x = h2u(__floats2half2_rn(a.x, bb.x));
                u.y = h2u(__floats2half2_rn(a.y, bb.y));
                u.z = h2u(__floats2half2_rn(a.z, bb.z));
                u.w = h2u(__floats2half2_rn(a.w, bb.w));
                *(uint4*)&Vs2[pr * VLD_ + d] = u;
            }
        }
        __syncthreads();

#pragma unroll
        for (int kq = 0; kq < 2; kq++) {
            const int co = kq * 16 + 4 * c;
            uint32_t bf[4][2];
#pragma unroll
            for (int ni = 0; ni < 4; ni++) {
                const int col = wn + ni * 8 + g;
                bf[ni][0] = Vs2[(kq * 8 + c)     * VLD_ + col];
                bf[ni][1] = Vs2[(kq * 8 + c + 4) * VLD_ + col];
            }
#pragma unroll
            for (int mi = 0; mi < 4; mi++) {
                const int row = wm + mi * 16 + g;
                const uint2 alo = *(const uint2*)&Ph[row * HLD_ + co];
                const uint2 ahi = *(const uint2*)&Ph[(row + 8) * HLD_ + co];
#pragma unroll
                for (int ni = 0; ni < 4; ni++)
                    mma16(acc[mi][ni], alo.x, ahi.x, alo.y, ahi.y, bf[ni][0], bf[ni][1]);
            }
        }
        __syncthreads();
    }

#pragma unroll
    for (int mi = 0; mi < 4; mi++) {
#pragma unroll
        for (int rr = 0; rr < 2; rr++) {
            const int qrow = qt + wm + mi * 16 + g + rr * 8;
            float* orow = out + ((size_t)b * S_ + qrow) * D_;
#pragma unroll
            for (int ni = 0; ni < 4; ni++) {
                const int col = wn + ni * 8 + c * 2;
                float2 o = { acc[mi][ni][rr * 2 + 0], acc[mi][ni][rr * 2 + 1] };
                *(float2*)&orow[col] = o;
            }
        }
    }
}

// =====================================================================
// d_out = [output (B*S*D) | attn (B*S*S)]
// =====================================================================
extern "C" void kernel_launch(void* const* d_in, const int* in_sizes, int n_in,
                              void* d_out, int out_size)
{
    const float* q    = (const float*)d_in[0];
    const float* k    = (const float*)d_in[1];
    const float* v    = (const float*)d_in[2];
    const float* mask = (const float*)d_in[3];

    float* out  = (float*)d_out;
    float* attn = out + (size_t)B_ * S_ * D_;

    cudaFuncSetAttribute(scores_mma, cudaFuncAttributeMaxDynamicSharedMemorySize, S_SMEM);

    dim3 g1(B_, S_ / 128, S_ / 128);   // b fastest -> L2 reuse of Q/K/mask tiles
    scores_mma<<<g1, 128, S_SMEM>>>(q, k, mask, attn);

    softmax_kernel<<<B_ * S_, 256>>>(attn);

    dim3 g3(B_, S_ / 128);
    out_mma<<<g3, 256>>>(attn, v, out);
}

// round 13
// speedup vs baseline: 1.0442x; 1.0442x over previous
#include <cuda_runtime.h>
#include <cuda_fp16.h>
#include <cstdint>

#define B_ 16
#define S_ 2048
#define D_ 128
#define SCALE_ 0.08838834764831845f  // 1/sqrt(128)

#define QLD_ 136   // halves per Q/K smem row (128 data + 8 pad)
#define CLD_ 132   // floats per staging row (128 data + 4 pad)
#define HLD_ 48    // halves per P smem row (32 data + 16 pad)
#define VLD_ 136   // words per Vs2 row (128 data + 8 pad)

__device__ __forceinline__ uint32_t h2u(half2 h) {
    union { half2 h; uint32_t u; } cvt;
    cvt.h = h;
    return cvt.u;
}

__device__ __forceinline__ uint32_t smem_u32(const void* p) {
    uint32_t a;
    asm("{ .reg .u64 t; cvta.to.shared.u64 t, %1; cvt.u32.u64 %0, t; }" : "=r"(a) : "l"(p));
    return a;
}

// D += A*B, m16n8k16 f16 (f32 accum)
__device__ __forceinline__ void mma16(float* d, uint32_t a0, uint32_t a1, uint32_t a2,
                                      uint32_t a3, uint32_t b0, uint32_t b1) {
    asm volatile(
        "mma.sync.aligned.m16n8k16.row.col.f32.f16.f16.f32 "
        "{%0,%1,%2,%3}, {%4,%5,%6,%7}, {%8,%9}, {%0,%1,%2,%3};"
        : "+f"(d[0]), "+f"(d[1]), "+f"(d[2]), "+f"(d[3])
        : "r"(a0), "r"(a1), "r"(a2), "r"(a3), "r"(b0), "r"(b1));
}

#define LDSM4(r0, r1, r2, r3, a) \
    asm volatile("ldmatrix.sync.aligned.m8n8.x4.shared.b16 {%0,%1,%2,%3}, [%4];" \
                 : "=r"(r0), "=r"(r1), "=r"(r2), "=r"(r3) : "r"(a))

// Convert float4 -> 4 halves, one STS.64
__device__ __forceinline__ void store_h4(half* rowp, int c4, float4 v) {
    uint2 u = { h2u(__floats2half2_rn(v.x, v.y)), h2u(__floats2half2_rn(v.z, v.w)) };
    *(uint2*)(rowp + c4) = u;
}

// Permuted half store (out_mma P layout)
__device__ __forceinline__ void store_perm(half* rowp, int c4, float4 v) {
    const int kk0 = c4 & 15;
    const int pos = ((c4 >> 4) << 4) + ((kk0 & 7) << 1) + ((kk0 >> 3) << 1);
    *(half2*)(rowp + pos)     = __floats2half2_rn(v.x, v.y);
    *(half2*)(rowp + pos + 4) = __floats2half2_rn(v.z, v.w);
}

// =====================================================================
// Kernel 1: scores[b,q,k] = (Q.K^T)*SCALE + mask
// CTA 128x128, full-depth single fill, barrier-free mainloop (round-11),
// NEW: smem-staged epilogue -> fully coalesced mask loads & attn stores.
// 8 warps = 2(m) x 4(n); warp tile 64x32.
// =====================================================================
#define S_SMEM (2 * 128 * QLD_ * 2)   // 69632 B >= 128*CLD_*4 = 67584 B

__global__ __launch_bounds__(256, 2) void scores_mma(
    const float* __restrict__ q, const float* __restrict__ k,
    const float* __restrict__ mask, float* __restrict__ attn)
{
    extern __shared__ half sm[];
    half* Qh = sm;                 // [128][QLD_]
    half* Kh = sm + 128 * QLD_;    // [128][QLD_]
    float* Cs = (float*)sm;        // staging, aliases Qh/Kh after mainloop

    const int b  = blockIdx.x;
    const int kt = blockIdx.y * 128;
    const int qt = blockIdx.z * 128;

    const float* qb = q + ((size_t)b * S_ + qt) * D_;
    const float* kb = k + ((size_t)b * S_ + kt) * D_;

    const int tid  = threadIdx.x;
    const int wid  = tid >> 5, lane = tid & 31;
    const int g    = lane >> 2, c = lane & 3;
    const int wm   = (wid & 1) * 64;
    const int wn   = (wid >> 1) * 32;

    const uint32_t qbase = smem_u32(Qh);
    const uint32_t kbase = smem_u32(Kh);
    const int l15 = lane & 15;
    const int khi = (lane >> 4) << 3;

    float acc[4][4][4];
#pragma unroll
    for (int mi = 0; mi < 4; mi++)
#pragma unroll
        for (int ni = 0; ni < 4; ni++)
#pragma unroll
            for (int r = 0; r < 4; r++) acc[mi][ni][r] = 0.0f;

    // ---- single fill: full 128x128 Q and K tiles ----
#pragma unroll
    for (int t = 0; t < 16; t++) {
        const int idx = tid + t * 256;
        const int row = idx >> 5, c4 = (idx & 31) * 4;
        const float4 vq = *(const float4*)&qb[(size_t)row * D_ + c4];
        store_h4(&Qh[row * QLD_], c4, vq);
    }
#pragma unroll
    for (int t = 0; t < 16; t++) {
        const int idx = tid + t * 256;
        const int row = idx >> 5, c4 = (idx & 31) * 4;
        const float4 vk = *(const float4*)&kb[(size_t)row * D_ + c4];
        store_h4(&Kh[row * QLD_], c4, vk);
    }
    __syncthreads();

    // ---- 8 k-steps, no barriers ----
#pragma unroll
    for (int kq = 0; kq < 8; kq++) {
        const int koff = kq * 16 + khi;
        uint32_t b0[4], b1[4];
#pragma unroll
        for (int bg = 0; bg < 2; bg++) {
            const uint32_t a = kbase +
                (uint32_t)(((wn + bg * 16 + l15) * QLD_ + koff) << 1);
            LDSM4(b0[2 * bg], b0[2 * bg + 1], b1[2 * bg], b1[2 * bg + 1], a);
        }
#pragma unroll
        for (int mi = 0; mi < 4; mi++) {
            uint32_t a0, a1, a2, a3;
            const uint32_t a = qbase +
                (uint32_t)(((wm + mi * 16 + l15) * QLD_ + koff) << 1);
            LDSM4(a0, a1, a2, a3, a);
#pragma unroll
            for (int ni = 0; ni < 4; ni++)
                mma16(acc[mi][ni], a0, a1, a2, a3, b0[ni], b1[ni]);
        }
    }

    // ---- staged epilogue ----
    __syncthreads();   // all LDSM reads done before overwriting smem
#pragma unroll
    for (int mi = 0; mi < 4; mi++) {
#pragma unroll
        for (int rr = 0; rr < 2; rr++) {
            const int row = wm + mi * 16 + g + rr * 8;
#pragma unroll
            for (int ni = 0; ni < 4; ni++) {
                const int col = wn + ni * 8 + c * 2;
                *(float2*)&Cs[row * CLD_ + col] =
                    make_float2(acc[mi][ni][rr * 2 + 0], acc[mi][ni][rr * 2 + 1]);
            }
        }
    }
    __syncthreads();

    // each warp writes complete 512B rows: coalesced LDG mask + STG attn
    const int lane4 = lane * 4;
#pragma unroll
    for (int j = 0; j < 16; j++) {
        const int row = wid * 16 + j;
        const float4 cv = *(const float4*)&Cs[row * CLD_ + lane4];
        const float4 m4 = *(const float4*)&mask[(size_t)(qt + row) * S_ + kt + lane4];
        float4 o;
        o.x = cv.x * SCALE_ + m4.x;
        o.y = cv.y * SCALE_ + m4.y;
        o.z = cv.z * SCALE_ + m4.z;
        o.w = cv.w * SCALE_ + m4.w;
        *(float4*)&attn[((size_t)b * S_ + qt + row) * S_ + kt + lane4] = o;
    }
}

// =====================================================================
// Kernel 2: in-place row softmax. One 256-thread CTA per row.
// =====================================================================
__global__ __launch_bounds__(256) void softmax_kernel(float* __restrict__ attn)
{
    __shared__ float red[256];
    const size_t row = blockIdx.x;
    float* p = attn + row * (size_t)S_;
    const int tid = threadIdx.x;

    float4 v0 = ((const float4*)p)[tid];
    float4 v1 = ((const float4*)p)[tid + 256];

    float m = fmaxf(fmaxf(fmaxf(v0.x, v0.y), fmaxf(v0.z, v0.w)),
                    fmaxf(fmaxf(v1.x, v1.y), fmaxf(v1.z, v1.w)));
    red[tid] = m;
    __syncthreads();
#pragma unroll
    for (int s = 128; s > 0; s >>= 1) {
        if (tid < s) red[tid] = fmaxf(red[tid], red[tid + s]);
        __syncthreads();
    }
    m = red[0];
    __syncthreads();

    v0.x = __expf(v0.x - m); v0.y = __expf(v0.y - m);
    v0.z = __expf(v0.z - m); v0.w = __expf(v0.w - m);
    v1.x = __expf(v1.x - m); v1.y = __expf(v1.y - m);
    v1.z = __expf(v1.z - m); v1.w = __expf(v1.w - m);

    float sum = (v0.x + v0.y) + (v0.z + v0.w) + (v1.x + v1.y) + (v1.z + v1.w);
    red[tid] = sum;
    __syncthreads();
#pragma unroll
    for (int s = 128; s > 0; s >>= 1) {
        if (tid < s) red[tid] += red[tid + s];
        __syncthreads();
    }
    const float inv = 1.0f / red[0];

    v0.x *= inv; v0.y *= inv; v0.z *= inv; v0.w *= inv;
    v1.x *= inv; v1.y *= inv; v1.z *= inv; v1.w *= inv;
    ((float4*)p)[tid]       = v0;
    ((float4*)p)[tid + 256] = v1;
}

// =====================================================================
// Kernel 3: out[b,q,d] = sum_s P[b,q,s] * V[b,s,d]   (round-8/11 exact)
// =====================================================================
__global__ __launch_bounds__(256, 2) void out_mma(
    const float* __restrict__ attn, const float* __restrict__ v,
    float* __restrict__ out)
{
    __shared__ half Ph[128 * HLD_];
    __shared__ uint32_t Vs2[16 * VLD_];

    const int b  = blockIdx.x;
    const int qt = blockIdx.y * 128;

    const float* pb = attn + ((size_t)b * S_ + qt) * S_;
    const float* vb = v + (size_t)b * S_ * D_;

    const int tid  = threadIdx.x;
    const int wid  = tid >> 5, lane = tid & 31;
    const int g    = lane >> 2, c = lane & 3;
    const int wm   = (wid & 1) * 64;
    const int wn   = (wid >> 1) * 32;

    const int pr    = tid >> 4;
    const int dbase = (tid & 15) * 4;

    float acc[4][4][4];
#pragma unroll
    for (int mi = 0; mi < 4; mi++)
#pragma unroll
        for (int ni = 0; ni < 4; ni++)
#pragma unroll
            for (int r = 0; r < 4; r++) acc[mi][ni][r] = 0.0f;

#pragma unroll 1
    for (int k0 = 0; k0 < S_; k0 += 32) {
#pragma unroll
        for (int t = 0; t < 4; t++) {
            const int idx = tid + t * 256;
            const int row = idx >> 3, c4 = (idx & 7) * 4;
            const float4 vp = *(const float4*)&pb[(size_t)row * S_ + k0 + c4];
            store_perm(&Ph[row * HLD_], c4, vp);
        }
        {
            const float* v0r = vb + (size_t)(k0 + 2 * pr) * D_;
            const float* v1r = v0r + D_;
#pragma unroll
            for (int h = 0; h < 2; h++) {
                const int d = dbase + h * 64;
                const float4 a = *(const float4*)&v0r[d];
                const float4 bb = *(const float4*)&v1r[d];
                uint4 u;
                u.x = h2u(__floats2half2_rn(a.x, bb.x));
                u.y = h2u(__floats2half2_rn(a.y, bb.y));
                u.z = h2u(__floats2half2_rn(a.z, bb.z));
                u.w = h2u(__floats2half2_rn(a.w, bb.w));
                *(uint4*)&Vs2[pr * VLD_ + d] = u;
            }
        }
        __syncthreads();

#pragma unroll
        for (int kq = 0; kq < 2; kq++) {
            const int co = kq * 16 + 4 * c;
            uint32_t bf[4][2];
#pragma unroll
            for (int ni = 0; ni < 4; ni++) {
                const int col = wn + ni * 8 + g;
                bf[ni][0] = Vs2[(kq * 8 + c)     * VLD_ + col];
                bf[ni][1] = Vs2[(kq * 8 + c + 4) * VLD_ + col];
            }
#pragma unroll
            for (int mi = 0; mi < 4; mi++) {
                const int row = wm + mi * 16 + g;
                const uint2 alo = *(const uint2*)&Ph[row * HLD_ + co];
                const uint2 ahi = *(const uint2*)&Ph[(row + 8) * HLD_ + co];
#pragma unroll
                for (int ni = 0; ni < 4; ni++)
                    mma16(acc[mi][ni], alo.x, ahi.x, alo.y, ahi.y, bf[ni][0], bf[ni][1]);
            }
        }
        __syncthreads();
    }

#pragma unroll
    for (int mi = 0; mi < 4; mi++) {
#pragma unroll
        for (int rr = 0; rr < 2; rr++) {
            const int qrow = qt + wm + mi * 16 + g + rr * 8;
            float* orow = out + ((size_t)b * S_ + qrow) * D_;
#pragma unroll
            for (int ni = 0; ni < 4; ni++) {
                const int col = wn + ni * 8 + c * 2;
                float2 o = { acc[mi][ni][rr * 2 + 0], acc[mi][ni][rr * 2 + 1] };
                *(float2*)&orow[col] = o;
            }
        }
    }
}

// =====================================================================
// d_out = [output (B*S*D) | attn (B*S*S)]
// =====================================================================
extern "C" void kernel_launch(void* const* d_in, const int* in_sizes, int n_in,
                              void* d_out, int out_size)
{
    const float* q    = (const float*)d_in[0];
    const float* k    = (const float*)d_in[1];
    const float* v    = (const float*)d_in[2];
    const float* mask = (const float*)d_in[3];

    float* out  = (float*)d_out;
    float* attn = out + (size_t)B_ * S_ * D_;

    cudaFuncSetAttribute(scores_mma, cudaFuncAttributeMaxDynamicSharedMemorySize, S_SMEM);

    dim3 g1(B_, S_ / 128, S_ / 128);   // b fastest -> L2 reuse of Q/K/mask tiles
    scores_mma<<<g1, 256, S_SMEM>>>(q, k, mask, attn);

    softmax_kernel<<<B_ * S_, 256>>>(attn);

    dim3 g3(B_, S_ / 128);
    out_mma<<<g3, 256>>>(attn, v, out);
}